// round 1
// baseline (speedup 1.0000x reference)
#include <cuda_runtime.h>
#include <math.h>

// Problem constants (fixed by the reference spec)
//   IN_FEATURES=128, UNITS=512, BATCH=2048, out = [x (2048*128) ; logdet (2048)]
#define R        16      // rows per CTA
#define RP       20      // padded per-unit row stride in smem (floats) - kills bank conflicts
#define THREADS  256
#define NBLK     128     // 2048 / 16

// ---- device scratch (static, no allocation) ----
__device__ float g_W1c[128 * 512];   // [i][p]  masked W1, permuted hidden, input-major
__device__ float g_W2t[512 * 512];   // [p][q]  masked W2, both dims permuted, p-major
__device__ float g_W3t[512 * 256];   // [q][o]  masked W3, hidden permuted, q-major
__device__ float g_A1init[512];      // b1 permuted (pre-act at x=0)
__device__ float g_A2init[512];      // pre-act-2 at x=0
__device__ float g_Zinit[256];       // z at x=0

// degree of hidden unit k is k % 127; sorted-by-degree position:
__device__ __forceinline__ int posOf(int k) {
    int d = k % 127;
    int j = k / 127;
    return d * 4 + (d < 4 ? d : 4) + j;
}
// inverse permutation: sorted position q -> original index
__device__ __forceinline__ int origOf(int q) {
    int d, j;
    if (q < 20) { d = q / 5; j = q - d * 5; }
    else        { d = 4 + ((q - 20) >> 2); j = (q - 20) & 3; }
    return d + 127 * j;
}

// ---------------- prologue: mask + permute + transpose weights ----------------
__global__ void k_transform(const float* __restrict__ W1, const float* __restrict__ b1,
                            const float* __restrict__ W2, const float* __restrict__ W3,
                            const float* __restrict__ m1, const float* __restrict__ m2,
                            const float* __restrict__ m3) {
    int idx = blockIdx.x * blockDim.x + threadIdx.x;
    int stride = gridDim.x * blockDim.x;
    // W1: [512,128] row-major -> g_W1c[i*512 + pos(k)]
    for (int t = idx; t < 512 * 128; t += stride) {
        int k = t >> 7, i = t & 127;
        g_W1c[i * 512 + posOf(k)] = W1[t] * m1[t];
    }
    // W2: [512,512] (m,k) -> g_W2t[pos(k)*512 + pos(m)]
    for (int t = idx; t < 512 * 512; t += stride) {
        int m = t >> 9, k = t & 511;
        g_W2t[posOf(k) * 512 + posOf(m)] = W2[t] * m2[t];
    }
    // W3: [256,512] (o,m) -> g_W3t[pos(m)*256 + o]
    for (int t = idx; t < 256 * 512; t += stride) {
        int o = t >> 9, m = t & 511;
        g_W3t[posOf(m) * 256 + o] = W3[t] * m3[t];
    }
    for (int t = idx; t < 512; t += stride)
        g_A1init[posOf(t)] = b1[t];
}

// initial state at x = 0 (shared by every batch row)
__global__ void k_init(const float* __restrict__ b2, const float* __restrict__ b3) {
    __shared__ float h1[512], h2[512];
    int t = threadIdx.x;   // 512 threads
    h1[t] = fmaxf(g_A1init[t], 0.f);
    __syncthreads();
    {
        float acc = b2[origOf(t)];
        for (int p = 0; p < 512; ++p) acc = fmaf(g_W2t[p * 512 + t], h1[p], acc);
        g_A2init[t] = acc;
        h2[t] = fmaxf(acc, 0.f);
    }
    __syncthreads();
    if (t < 256) {
        float a = b3[t];
        for (int q = 0; q < 512; ++q) a = fmaf(g_W3t[q * 256 + t], h2[q], a);
        g_Zinit[t] = a;
    }
}

// ---------------- main persistent kernel: 128 CTAs x 16 rows ----------------
__global__ void __launch_bounds__(THREADS, 1)
k_main(const float* __restrict__ u, float* __restrict__ out) {
    extern __shared__ float sm[];
    float* A1  = sm;                 // 512*RP  pre-act layer 1
    float* A2  = A1 + 512 * RP;      // 512*RP  pre-act layer 2
    float* DH1 = A2 + 512 * RP;      // 512*RP  relu deltas layer 1
    float* DH2 = DH1 + 512 * RP;     // 512*RP  relu deltas layer 2
    float* Z   = DH2 + 512 * RP;     // 256*RP  output accumulators [mu;sigma]
    float* xi  = Z + 256 * RP;       // R       current x_i per row
    float* ld  = xi + R;             // R       logdet accum per row

    const int tid  = threadIdx.x;
    const int row0 = blockIdx.x * R;

    // replicate the x=0 state across the R rows
    for (int t = tid; t < 512; t += THREADS) {
        float a1 = g_A1init[t], a2 = g_A2init[t];
#pragma unroll
        for (int r = 0; r < R; ++r) { A1[t * RP + r] = a1; A2[t * RP + r] = a2; }
    }
    if (tid < 256) {
        float z = g_Zinit[tid];
#pragma unroll
        for (int r = 0; r < R; ++r) Z[tid * RP + r] = z;
    }
    if (tid < R) ld[tid] = 0.f;
    __syncthreads();

    for (int i = 0; i < 128; ++i) {
        // ---- (a) read z_i, produce x_i, accumulate logdet ----
        if (tid < R) {
            float mu = Z[i * RP + tid];
            float sg = Z[(128 + i) * RP + tid];
            float x  = u[(row0 + tid) * 128 + i] * expf(sg) + mu;
            xi[tid] = x;
            ld[tid] += sg;
            out[(row0 + tid) * 128 + i] = x;
        }
        __syncthreads();
        if (i == 127) break;

        const int s = 4 * i + (i < 4 ? i : 4);   // suffix start: units with degree >= i

        // ---- (c) layer-1 suffix update + relu delta ----
        {
            int r = tid & 15;
            for (int p = s + (tid >> 4); p < 512; p += 16) {
                float w   = g_W1c[i * 512 + p];
                float old = A1[p * RP + r];
                float nw  = fmaf(w, xi[r], old);
                A1[p * RP + r]  = nw;
                DH1[p * RP + r] = fmaxf(nw, 0.f) - fmaxf(old, 0.f);
            }
        }
        __syncthreads();

        // ---- (d) rank update: A2[q,:] += sum_p W2t[p][q] * DH1[p,:]  (suffix x suffix) ----
        {
            int q0 = s + tid * 2;
            if (q0 < 512) {
                const bool two = (q0 + 1) < 512;
                float acc0[R], acc1[R];
#pragma unroll
                for (int r = 0; r < R; ++r) { acc0[r] = 0.f; acc1[r] = 0.f; }
#pragma unroll 2
                for (int p = s; p < 512; ++p) {
                    float w0 = g_W2t[p * 512 + q0];
                    float w1 = two ? g_W2t[p * 512 + q0 + 1] : 0.f;
                    const float4* dh = (const float4*)(DH1 + p * RP);
                    float4 v0 = dh[0], v1 = dh[1], v2 = dh[2], v3 = dh[3];
                    acc0[ 0] = fmaf(w0, v0.x, acc0[ 0]); acc1[ 0] = fmaf(w1, v0.x, acc1[ 0]);
                    acc0[ 1] = fmaf(w0, v0.y, acc0[ 1]); acc1[ 1] = fmaf(w1, v0.y, acc1[ 1]);
                    acc0[ 2] = fmaf(w0, v0.z, acc0[ 2]); acc1[ 2] = fmaf(w1, v0.z, acc1[ 2]);
                    acc0[ 3] = fmaf(w0, v0.w, acc0[ 3]); acc1[ 3] = fmaf(w1, v0.w, acc1[ 3]);
                    acc0[ 4] = fmaf(w0, v1.x, acc0[ 4]); acc1[ 4] = fmaf(w1, v1.x, acc1[ 4]);
                    acc0[ 5] = fmaf(w0, v1.y, acc0[ 5]); acc1[ 5] = fmaf(w1, v1.y, acc1[ 5]);
                    acc0[ 6] = fmaf(w0, v1.z, acc0[ 6]); acc1[ 6] = fmaf(w1, v1.z, acc1[ 6]);
                    acc0[ 7] = fmaf(w0, v1.w, acc0[ 7]); acc1[ 7] = fmaf(w1, v1.w, acc1[ 7]);
                    acc0[ 8] = fmaf(w0, v2.x, acc0[ 8]); acc1[ 8] = fmaf(w1, v2.x, acc1[ 8]);
                    acc0[ 9] = fmaf(w0, v2.y, acc0[ 9]); acc1[ 9] = fmaf(w1, v2.y, acc1[ 9]);
                    acc0[10] = fmaf(w0, v2.z, acc0[10]); acc1[10] = fmaf(w1, v2.z, acc1[10]);
                    acc0[11] = fmaf(w0, v2.w, acc0[11]); acc1[11] = fmaf(w1, v2.w, acc1[11]);
                    acc0[12] = fmaf(w0, v3.x, acc0[12]); acc1[12] = fmaf(w1, v3.x, acc1[12]);
                    acc0[13] = fmaf(w0, v3.y, acc0[13]); acc1[13] = fmaf(w1, v3.y, acc1[13]);
                    acc0[14] = fmaf(w0, v3.z, acc0[14]); acc1[14] = fmaf(w1, v3.z, acc1[14]);
                    acc0[15] = fmaf(w0, v3.w, acc0[15]); acc1[15] = fmaf(w1, v3.w, acc1[15]);
                }
#pragma unroll
                for (int r = 0; r < R; ++r) {
                    float old = A2[q0 * RP + r];
                    float nw  = old + acc0[r];
                    A2[q0 * RP + r]  = nw;
                    DH2[q0 * RP + r] = fmaxf(nw, 0.f) - fmaxf(old, 0.f);
                }
                if (two) {
#pragma unroll
                    for (int r = 0; r < R; ++r) {
                        float old = A2[(q0 + 1) * RP + r];
                        float nw  = old + acc1[r];
                        A2[(q0 + 1) * RP + r]  = nw;
                        DH2[(q0 + 1) * RP + r] = fmaxf(nw, 0.f) - fmaxf(old, 0.f);
                    }
                }
            }
        }
        __syncthreads();

        // ---- (e) z update for future outputs: o in (i,128) and (128+i,256) ----
        {
            int half = 127 - i;
            if (tid < 2 * half) {
                int o = (tid < half) ? (i + 1 + tid) : (129 + i + (tid - half));
                float acc[R];
#pragma unroll
                for (int r = 0; r < R; ++r) acc[r] = 0.f;
#pragma unroll 2
                for (int q = s; q < 512; ++q) {
                    float w = g_W3t[q * 256 + o];
                    const float4* dh = (const float4*)(DH2 + q * RP);
                    float4 v0 = dh[0], v1 = dh[1], v2 = dh[2], v3 = dh[3];
                    acc[ 0] = fmaf(w, v0.x, acc[ 0]);
                    acc[ 1] = fmaf(w, v0.y, acc[ 1]);
                    acc[ 2] = fmaf(w, v0.z, acc[ 2]);
                    acc[ 3] = fmaf(w, v0.w, acc[ 3]);
                    acc[ 4] = fmaf(w, v1.x, acc[ 4]);
                    acc[ 5] = fmaf(w, v1.y, acc[ 5]);
                    acc[ 6] = fmaf(w, v1.z, acc[ 6]);
                    acc[ 7] = fmaf(w, v1.w, acc[ 7]);
                    acc[ 8] = fmaf(w, v2.x, acc[ 8]);
                    acc[ 9] = fmaf(w, v2.y, acc[ 9]);
                    acc[10] = fmaf(w, v2.z, acc[10]);
                    acc[11] = fmaf(w, v2.w, acc[11]);
                    acc[12] = fmaf(w, v3.x, acc[12]);
                    acc[13] = fmaf(w, v3.y, acc[13]);
                    acc[14] = fmaf(w, v3.z, acc[14]);
                    acc[15] = fmaf(w, v3.w, acc[15]);
                }
#pragma unroll
                for (int r = 0; r < R; ++r) Z[o * RP + r] += acc[r];
            }
        }
        __syncthreads();
    }

    // logdet output
    if (tid < R) out[2048 * 128 + row0 + tid] = ld[tid];
}

extern "C" void kernel_launch(void* const* d_in, const int* in_sizes, int n_in,
                              void* d_out, int out_size) {
    const float* u  = (const float*)d_in[0];
    const float* W1 = (const float*)d_in[1];
    const float* b1 = (const float*)d_in[2];
    const float* W2 = (const float*)d_in[3];
    const float* b2 = (const float*)d_in[4];
    const float* W3 = (const float*)d_in[5];
    const float* b3 = (const float*)d_in[6];
    const float* m1 = (const float*)d_in[7];
    const float* m2 = (const float*)d_in[8];
    const float* m3 = (const float*)d_in[9];
    float* out = (float*)d_out;

    const size_t smem = (size_t)(512 * RP * 4 + 256 * RP + 2 * R) * sizeof(float); // 184448 B
    cudaFuncSetAttribute(k_main, cudaFuncAttributeMaxDynamicSharedMemorySize, (int)smem);

    k_transform<<<256, 256>>>(W1, b1, W2, W3, m1, m2, m3);
    k_init<<<1, 512>>>(b2, b3);
    k_main<<<NBLK, THREADS, smem>>>(u, out);
}

// round 2
// speedup vs baseline: 1.9139x; 1.9139x over previous
#include <cuda_runtime.h>
#include <math.h>

// IN_FEATURES=128, UNITS=512, BATCH=2048, out = [x (2048*128) ; logdet (2048)]
#define R        16      // rows per CTA
#define RP       20      // padded per-unit row stride in smem (floats)
#define US       132     // padded u-row stride (conflict-free column reads)
#define THREADS  512
#define NBLK     128     // 2048 / 16

// ---- device scratch (static, no allocation) ----
__device__ float g_W1c[128 * 512];   // [i][p]  masked W1, permuted hidden
__device__ float g_W2t[512 * 512];   // [p][q]  masked W2, both dims permuted
__device__ float g_W3t[512 * 256];   // [q][o]  masked W3, hidden permuted
__device__ float g_A1init[512];
__device__ float g_A2init[512];
__device__ float g_Zinit[256];

// degree of hidden unit k is k % 127; sorted-by-degree position:
__device__ __forceinline__ int posOf(int k) {
    int d = k % 127;
    int j = k / 127;
    return d * 4 + (d < 4 ? d : 4) + j;
}
__device__ __forceinline__ int origOf(int q) {
    int d, j;
    if (q < 20) { d = q / 5; j = q - d * 5; }
    else        { d = 4 + ((q - 20) >> 2); j = (q - 20) & 3; }
    return d + 127 * j;
}

// ---------------- prologue: mask + permute + transpose weights ----------------
__global__ void k_transform(const float* __restrict__ W1, const float* __restrict__ b1,
                            const float* __restrict__ W2, const float* __restrict__ W3,
                            const float* __restrict__ m1, const float* __restrict__ m2,
                            const float* __restrict__ m3) {
    int idx = blockIdx.x * blockDim.x + threadIdx.x;
    int stride = gridDim.x * blockDim.x;
    for (int t = idx; t < 512 * 128; t += stride) {
        int k = t >> 7, i = t & 127;
        g_W1c[i * 512 + posOf(k)] = W1[t] * m1[t];
    }
    for (int t = idx; t < 512 * 512; t += stride) {
        int m = t >> 9, k = t & 511;
        g_W2t[posOf(k) * 512 + posOf(m)] = W2[t] * m2[t];
    }
    for (int t = idx; t < 256 * 512; t += stride) {
        int o = t >> 9, m = t & 511;
        g_W3t[posOf(m) * 256 + o] = W3[t] * m3[t];
    }
    for (int t = idx; t < 512; t += stride)
        g_A1init[posOf(t)] = b1[t];
}

__global__ void k_init(const float* __restrict__ b2, const float* __restrict__ b3) {
    __shared__ float h1[512], h2[512];
    int t = threadIdx.x;   // 512 threads
    h1[t] = fmaxf(g_A1init[t], 0.f);
    __syncthreads();
    {
        float acc = b2[origOf(t)];
        for (int p = 0; p < 512; ++p) acc = fmaf(g_W2t[p * 512 + t], h1[p], acc);
        g_A2init[t] = acc;
        h2[t] = fmaxf(acc, 0.f);
    }
    __syncthreads();
    if (t < 256) {
        float a = b3[t];
        for (int q = 0; q < 512; ++q) a = fmaf(g_W3t[q * 256 + t], h2[q], a);
        g_Zinit[t] = a;
    }
}

// FMA a 16-row smem vector (float4 x4) into 16 accumulators with weight w
__device__ __forceinline__ void fma16(float* acc, const float* base, float w) {
    const float4* v = (const float4*)base;
    float4 v0 = v[0], v1 = v[1], v2 = v[2], v3 = v[3];
    acc[ 0] = fmaf(w, v0.x, acc[ 0]); acc[ 1] = fmaf(w, v0.y, acc[ 1]);
    acc[ 2] = fmaf(w, v0.z, acc[ 2]); acc[ 3] = fmaf(w, v0.w, acc[ 3]);
    acc[ 4] = fmaf(w, v1.x, acc[ 4]); acc[ 5] = fmaf(w, v1.y, acc[ 5]);
    acc[ 6] = fmaf(w, v1.z, acc[ 6]); acc[ 7] = fmaf(w, v1.w, acc[ 7]);
    acc[ 8] = fmaf(w, v2.x, acc[ 8]); acc[ 9] = fmaf(w, v2.y, acc[ 9]);
    acc[10] = fmaf(w, v2.z, acc[10]); acc[11] = fmaf(w, v2.w, acc[11]);
    acc[12] = fmaf(w, v3.x, acc[12]); acc[13] = fmaf(w, v3.y, acc[13]);
    acc[14] = fmaf(w, v3.z, acc[14]); acc[15] = fmaf(w, v3.w, acc[15]);
}

// ---------------- main persistent kernel: 128 CTAs x 16 rows ----------------
__global__ void __launch_bounds__(THREADS, 1)
k_main(const float* __restrict__ u, float* __restrict__ out) {
    extern __shared__ float sm[];
    float* A1  = sm;                 // 512*RP
    float* A2  = A1 + 512 * RP;      // 512*RP
    float* DH1 = A2 + 512 * RP;      // 512*RP
    float* DH2 = DH1 + 512 * RP;     // 512*RP
    float* Z   = DH2 + 512 * RP;     // 256*RP
    float* us  = Z + 256 * RP;       // R*US   u rows, padded
    float* xi  = us + R * US;        // R
    float* ld  = xi + R;             // R

    const int tid  = threadIdx.x;
    const int row0 = blockIdx.x * R;

    // preload u rows (coalesced)
    for (int t = tid; t < R * 128; t += THREADS) {
        int r = t >> 7, c = t & 127;
        us[r * US + c] = u[(row0 + r) * 128 + c];
    }
    // replicate x=0 state across rows
    for (int t = tid; t < 512; t += THREADS) {
        float a1 = g_A1init[t], a2 = g_A2init[t];
#pragma unroll
        for (int r = 0; r < R; ++r) { A1[t * RP + r] = a1; A2[t * RP + r] = a2; }
    }
    for (int t = tid; t < 256; t += THREADS) {
        float z = g_Zinit[t];
#pragma unroll
        for (int r = 0; r < R; ++r) Z[t * RP + r] = z;
    }
    if (tid < R) ld[tid] = 0.f;
    __syncthreads();

    for (int i = 0; i < 128; ++i) {
        // ---- (a) x_i = u_i * exp(sigma_i) + mu_i ----
        if (tid < R) {
            float mu = Z[i * RP + tid];
            float sg = Z[(128 + i) * RP + tid];
            float x  = us[tid * US + i] * expf(sg) + mu;
            xi[tid] = x;
            ld[tid] += sg;
            out[(row0 + tid) * 128 + i] = x;
        }
        __syncthreads();
        if (i == 127) break;

        const int s    = 4 * i + (i < 4 ? i : 4);   // suffix start
        const int cols = 512 - s;

        // ---- (c) layer-1 suffix update + relu delta ----
        {
            int r = tid & 15;
            for (int p = s + (tid >> 4); p < 512; p += THREADS / 16) {
                float w   = g_W1c[i * 512 + p];
                float old = A1[p * RP + r];
                float nw  = fmaf(w, xi[r], old);
                A1[p * RP + r]  = nw;
                DH1[p * RP + r] = fmaxf(nw, 0.f) - fmaxf(old, 0.f);
            }
        }
        __syncthreads();

        // ---- (d) A2[q,:] += sum_p W2t[p][q] * DH1[p,:] ----
        if (cols > 256) {
            // one column per thread
            if (tid < cols) {
                int q = s + tid;
                float acc[R];
#pragma unroll
                for (int r = 0; r < R; ++r) acc[r] = 0.f;
#pragma unroll 4
                for (int p = s; p < 512; ++p)
                    fma16(acc, DH1 + p * RP, g_W2t[p * 512 + q]);
#pragma unroll
                for (int r = 0; r < R; ++r) {
                    float old = A2[q * RP + r];
                    float nw  = old + acc[r];
                    A2[q * RP + r]  = nw;
                    DH2[q * RP + r] = fmaxf(nw, 0.f) - fmaxf(old, 0.f);
                }
            }
        } else {
            // two threads per column, split p-range, shuffle combine
            int active = 2 * cols;
            if (tid < ((active + 31) & ~31)) {
                int j    = tid >> 1;
                int half = tid & 1;
                int q    = s + (j < cols ? j : cols - 1);  // clamp for pad lanes
                int mid  = s + (cols >> 1);
                int p0   = half ? mid : s;
                int p1   = half ? 512 : mid;
                float acc[R];
#pragma unroll
                for (int r = 0; r < R; ++r) acc[r] = 0.f;
#pragma unroll 4
                for (int p = p0; p < p1; ++p)
                    fma16(acc, DH1 + p * RP, g_W2t[p * 512 + q]);
#pragma unroll
                for (int r = 0; r < R; ++r)
                    acc[r] += __shfl_xor_sync(0xffffffffu, acc[r], 1);
                if (half == 0 && j < cols) {
#pragma unroll
                    for (int r = 0; r < R; ++r) {
                        float old = A2[q * RP + r];
                        float nw  = old + acc[r];
                        A2[q * RP + r]  = nw;
                        DH2[q * RP + r] = fmaxf(nw, 0.f) - fmaxf(old, 0.f);
                    }
                }
            }
        }
        __syncthreads();

        // ---- (e) z update for future outputs, 2 threads per o ----
        {
            int hc     = 127 - i;          // future mu outputs
            int ocnt   = 2 * hc;           // + future sigma outputs
            int active = 2 * ocnt;
            if (tid < ((active + 31) & ~31)) {
                int j    = tid >> 1;
                int half = tid & 1;
                int jj   = (j < ocnt) ? j : ocnt - 1;      // clamp for pad lanes
                int o    = (jj < hc) ? (i + 1 + jj) : (129 + i + (jj - hc));
                int mid  = s + (cols >> 1);
                int q0   = half ? mid : s;
                int q1   = half ? 512 : mid;
                float acc[R];
#pragma unroll
                for (int r = 0; r < R; ++r) acc[r] = 0.f;
#pragma unroll 4
                for (int q = q0; q < q1; ++q)
                    fma16(acc, DH2 + q * RP, g_W3t[q * 256 + o]);
#pragma unroll
                for (int r = 0; r < R; ++r)
                    acc[r] += __shfl_xor_sync(0xffffffffu, acc[r], 1);
                if (half == 0 && j < ocnt) {
#pragma unroll
                    for (int r = 0; r < R; ++r) Z[o * RP + r] += acc[r];
                }
            }
        }
        __syncthreads();
    }

    if (tid < R) out[2048 * 128 + row0 + tid] = ld[tid];
}

extern "C" void kernel_launch(void* const* d_in, const int* in_sizes, int n_in,
                              void* d_out, int out_size) {
    const float* u  = (const float*)d_in[0];
    const float* W1 = (const float*)d_in[1];
    const float* b1 = (const float*)d_in[2];
    const float* W2 = (const float*)d_in[3];
    const float* b2 = (const float*)d_in[4];
    const float* W3 = (const float*)d_in[5];
    const float* b3 = (const float*)d_in[6];
    const float* m1 = (const float*)d_in[7];
    const float* m2 = (const float*)d_in[8];
    const float* m3 = (const float*)d_in[9];
    float* out = (float*)d_out;

    const size_t smem = (size_t)(512 * RP * 4 + 256 * RP + R * US + 2 * R) * sizeof(float);
    cudaFuncSetAttribute(k_main, cudaFuncAttributeMaxDynamicSharedMemorySize, (int)smem);

    k_transform<<<256, 256>>>(W1, b1, W2, W3, m1, m2, m3);
    k_init<<<1, 512>>>(b2, b3);
    k_main<<<NBLK, THREADS, smem>>>(u, out);
}

// round 3
// speedup vs baseline: 2.0713x; 1.0822x over previous
#include <cuda_runtime.h>
#include <math.h>

// IN_FEATURES=128, UNITS=512, BATCH=2048, out = [x (2048*128) ; logdet (2048)]
#define R        16      // rows per CTA
#define RP       20      // padded per-unit row stride in smem (floats)
#define US       132     // padded u-row stride
#define THREADS  512
#define NBLK     128     // 2048 / 16

typedef unsigned long long ull;

// ---- device scratch (static, no allocation) ----
__device__ float g_W1c[128 * 512];   // [i][p]  masked W1, permuted hidden
__device__ float g_W2t[512 * 512];   // [p][q]  masked W2, both dims permuted
__device__ float g_W3t[512 * 256];   // [q][o]  masked W3, hidden permuted
__device__ float g_A1init[512];
__device__ float g_A2init[512];
__device__ float g_Zinit[256];

// degree of hidden unit k is k % 127; sorted-by-degree position:
__device__ __forceinline__ int posOf(int k) {
    int d = k % 127;
    int j = k / 127;
    return d * 4 + (d < 4 ? d : 4) + j;
}
__device__ __forceinline__ int origOf(int q) {
    int d, j;
    if (q < 20) { d = q / 5; j = q - d * 5; }
    else        { d = 4 + ((q - 20) >> 2); j = (q - 20) & 3; }
    return d + 127 * j;
}

// ---------------- prologue kernels ----------------
__global__ void k_transform(const float* __restrict__ W1, const float* __restrict__ b1,
                            const float* __restrict__ W2, const float* __restrict__ W3,
                            const float* __restrict__ m1, const float* __restrict__ m2,
                            const float* __restrict__ m3) {
    int idx = blockIdx.x * blockDim.x + threadIdx.x;
    int stride = gridDim.x * blockDim.x;
    for (int t = idx; t < 512 * 128; t += stride) {
        int k = t >> 7, i = t & 127;
        g_W1c[i * 512 + posOf(k)] = W1[t] * m1[t];
    }
    for (int t = idx; t < 512 * 512; t += stride) {
        int m = t >> 9, k = t & 511;
        g_W2t[posOf(k) * 512 + posOf(m)] = W2[t] * m2[t];
    }
    for (int t = idx; t < 256 * 512; t += stride) {
        int o = t >> 9, m = t & 511;
        g_W3t[posOf(m) * 256 + o] = W3[t] * m3[t];
    }
    for (int t = idx; t < 512; t += stride)
        g_A1init[posOf(t)] = b1[t];
}

__global__ void k_init(const float* __restrict__ b2, const float* __restrict__ b3) {
    __shared__ float h1[512], h2[512];
    int t = threadIdx.x;   // 512 threads
    h1[t] = fmaxf(g_A1init[t], 0.f);
    __syncthreads();
    {
        float acc = b2[origOf(t)];
        for (int p = 0; p < 512; ++p) acc = fmaf(g_W2t[p * 512 + t], h1[p], acc);
        g_A2init[t] = acc;
        h2[t] = fmaxf(acc, 0.f);
    }
    __syncthreads();
    if (t < 256) {
        float a = b3[t];
        for (int q = 0; q < 512; ++q) a = fmaf(g_W3t[q * 256 + t], h2[q], a);
        g_Zinit[t] = a;
    }
}

// ---- packed f32x2 helpers ----
__device__ __forceinline__ ull dup2(float w) {
    ull r; asm("mov.b64 %0, {%1, %1};" : "=l"(r) : "f"(w)); return r;
}
__device__ __forceinline__ float2 u2f(ull v) {
    float2 f; asm("mov.b64 {%0, %1}, %2;" : "=f"(f.x), "=f"(f.y) : "l"(v)); return f;
}
// acc[0..7] (8 x packed pair = 16 rows) += w * smemvec[0..15]
__device__ __forceinline__ void fma8x2(ull* acc, const float* base, float w) {
    ull ww = dup2(w);
    const ulonglong2* v = (const ulonglong2*)base;   // 4 x LDS.128
    ulonglong2 a = v[0], b = v[1], c = v[2], d = v[3];
    asm("fma.rn.f32x2 %0, %1, %2, %0;" : "+l"(acc[0]) : "l"(ww), "l"(a.x));
    asm("fma.rn.f32x2 %0, %1, %2, %0;" : "+l"(acc[1]) : "l"(ww), "l"(a.y));
    asm("fma.rn.f32x2 %0, %1, %2, %0;" : "+l"(acc[2]) : "l"(ww), "l"(b.x));
    asm("fma.rn.f32x2 %0, %1, %2, %0;" : "+l"(acc[3]) : "l"(ww), "l"(b.y));
    asm("fma.rn.f32x2 %0, %1, %2, %0;" : "+l"(acc[4]) : "l"(ww), "l"(c.x));
    asm("fma.rn.f32x2 %0, %1, %2, %0;" : "+l"(acc[5]) : "l"(ww), "l"(c.y));
    asm("fma.rn.f32x2 %0, %1, %2, %0;" : "+l"(acc[6]) : "l"(ww), "l"(d.x));
    asm("fma.rn.f32x2 %0, %1, %2, %0;" : "+l"(acc[7]) : "l"(ww), "l"(d.y));
}
__device__ __forceinline__ void addp(ull& a, ull b) {
    asm("add.rn.f32x2 %0, %0, %1;" : "+l"(a) : "l"(b));
}

// ---------------- main persistent kernel: 128 CTAs x 16 rows ----------------
__global__ void __launch_bounds__(THREADS, 1)
k_main(const float* __restrict__ u, float* __restrict__ out) {
    extern __shared__ float sm[];
    float* A1  = sm;                 // 512*RP
    float* A2  = A1 + 512 * RP;      // 512*RP
    float* DH1 = A2 + 512 * RP;      // 512*RP
    float* DH2 = DH1 + 512 * RP;     // 512*RP
    float* Z   = DH2 + 512 * RP;     // 256*RP
    float* us  = Z + 256 * RP;       // R*US
    float* xi  = us + R * US;        // R
    float* ld  = xi + R;             // R

    const int tid  = threadIdx.x;
    const int row0 = blockIdx.x * R;

    for (int t = tid; t < R * 128; t += THREADS) {
        int r = t >> 7, c = t & 127;
        us[r * US + c] = u[(row0 + r) * 128 + c];
    }
    for (int t = tid; t < 512; t += THREADS) {
        float a1 = g_A1init[t], a2 = g_A2init[t];
#pragma unroll
        for (int r = 0; r < R; ++r) { A1[t * RP + r] = a1; A2[t * RP + r] = a2; }
    }
    for (int t = tid; t < 256; t += THREADS) {
        float z = g_Zinit[t];
#pragma unroll
        for (int r = 0; r < R; ++r) Z[t * RP + r] = z;
    }
    if (tid < R) ld[tid] = 0.f;
    __syncthreads();

    for (int i = 0; i < 128; ++i) {
        // ---- (a) x_i = u_i * exp(sigma_i) + mu_i ----
        if (tid < R) {
            float mu = Z[i * RP + tid];
            float sg = Z[(128 + i) * RP + tid];
            float x  = us[tid * US + i] * expf(sg) + mu;
            xi[tid] = x;
            ld[tid] += sg;
            out[(row0 + tid) * 128 + i] = x;
        }
        __syncthreads();
        if (i == 127) break;

        const int s    = 4 * i + (i < 4 ? i : 4);   // suffix start
        const int cols = 512 - s;

        // ---- (c) layer-1 suffix update + relu delta ----
        {
            int r = tid & 15;
            for (int p = s + (tid >> 4); p < 512; p += THREADS / 16) {
                float w   = g_W1c[i * 512 + p];
                float old = A1[p * RP + r];
                float nw  = fmaf(w, xi[r], old);
                A1[p * RP + r]  = nw;
                DH1[p * RP + r] = fmaxf(nw, 0.f) - fmaxf(old, 0.f);
            }
        }
        __syncthreads();

        // ---- (d) A2[q,:] += sum_p W2t[p][q] * DH1[p,:] ----
        if (cols > 256) {
            if (tid < cols) {
                int q = s + tid;
                ull acc[8];
#pragma unroll
                for (int k = 0; k < 8; ++k) acc[k] = 0ull;
#pragma unroll 4
                for (int p = s; p < 512; ++p)
                    fma8x2(acc, DH1 + p * RP, g_W2t[p * 512 + q]);
#pragma unroll
                for (int k = 0; k < 8; ++k) {
                    float2 a = u2f(acc[k]);
                    float o0 = A2[q * RP + 2 * k],     n0 = o0 + a.x;
                    float o1 = A2[q * RP + 2 * k + 1], n1 = o1 + a.y;
                    A2[q * RP + 2 * k]      = n0;
                    A2[q * RP + 2 * k + 1]  = n1;
                    DH2[q * RP + 2 * k]     = fmaxf(n0, 0.f) - fmaxf(o0, 0.f);
                    DH2[q * RP + 2 * k + 1] = fmaxf(n1, 0.f) - fmaxf(o1, 0.f);
                }
            }
        } else {
            // two threads per column, split p-range, shuffle combine
            int active = 2 * cols;
            if (tid < ((active + 31) & ~31)) {
                int j    = tid >> 1;
                int half = tid & 1;
                int q    = s + (j < cols ? j : cols - 1);
                int mid  = s + (cols >> 1);
                int p0   = half ? mid : s;
                int p1   = half ? 512 : mid;
                ull acc[8];
#pragma unroll
                for (int k = 0; k < 8; ++k) acc[k] = 0ull;
#pragma unroll 4
                for (int p = p0; p < p1; ++p)
                    fma8x2(acc, DH1 + p * RP, g_W2t[p * 512 + q]);
#pragma unroll
                for (int k = 0; k < 8; ++k)
                    addp(acc[k], __shfl_xor_sync(0xffffffffu, acc[k], 1));
                if (half == 0 && j < cols) {
#pragma unroll
                    for (int k = 0; k < 8; ++k) {
                        float2 a = u2f(acc[k]);
                        float o0 = A2[q * RP + 2 * k],     n0 = o0 + a.x;
                        float o1 = A2[q * RP + 2 * k + 1], n1 = o1 + a.y;
                        A2[q * RP + 2 * k]      = n0;
                        A2[q * RP + 2 * k + 1]  = n1;
                        DH2[q * RP + 2 * k]     = fmaxf(n0, 0.f) - fmaxf(o0, 0.f);
                        DH2[q * RP + 2 * k + 1] = fmaxf(n1, 0.f) - fmaxf(o1, 0.f);
                    }
                }
            }
        }
        __syncthreads();

        // ---- (e) z update for future outputs, 2 threads per o ----
        {
            int hc     = 127 - i;
            int ocnt   = 2 * hc;
            int active = 2 * ocnt;
            if (tid < ((active + 31) & ~31)) {
                int j    = tid >> 1;
                int half = tid & 1;
                int jj   = (j < ocnt) ? j : ocnt - 1;
                int o    = (jj < hc) ? (i + 1 + jj) : (129 + i + (jj - hc));
                int mid  = s + (cols >> 1);
                int q0   = half ? mid : s;
                int q1   = half ? 512 : mid;
                ull acc[8];
#pragma unroll
                for (int k = 0; k < 8; ++k) acc[k] = 0ull;
#pragma unroll 4
                for (int q = q0; q < q1; ++q)
                    fma8x2(acc, DH2 + q * RP, g_W3t[q * 256 + o]);
#pragma unroll
                for (int k = 0; k < 8; ++k)
                    addp(acc[k], __shfl_xor_sync(0xffffffffu, acc[k], 1));
                if (half == 0 && j < ocnt) {
#pragma unroll
                    for (int k = 0; k < 8; ++k) {
                        float2 a = u2f(acc[k]);
                        Z[o * RP + 2 * k]     += a.x;
                        Z[o * RP + 2 * k + 1] += a.y;
                    }
                }
            }
        }
        __syncthreads();
    }

    if (tid < R) out[2048 * 128 + row0 + tid] = ld[tid];
}

extern "C" void kernel_launch(void* const* d_in, const int* in_sizes, int n_in,
                              void* d_out, int out_size) {
    const float* u  = (const float*)d_in[0];
    const float* W1 = (const float*)d_in[1];
    const float* b1 = (const float*)d_in[2];
    const float* W2 = (const float*)d_in[3];
    const float* b2 = (const float*)d_in[4];
    const float* W3 = (const float*)d_in[5];
    const float* b3 = (const float*)d_in[6];
    const float* m1 = (const float*)d_in[7];
    const float* m2 = (const float*)d_in[8];
    const float* m3 = (const float*)d_in[9];
    float* out = (float*)d_out;

    const size_t smem = (size_t)(512 * RP * 4 + 256 * RP + R * US + 2 * R) * sizeof(float);
    cudaFuncSetAttribute(k_main, cudaFuncAttributeMaxDynamicSharedMemorySize, (int)smem);

    k_transform<<<256, 256>>>(W1, b1, W2, W3, m1, m2, m3);
    k_init<<<1, 512>>>(b2, b3);
    k_main<<<NBLK, THREADS, smem>>>(u, out);
}